// round 6
// baseline (speedup 1.0000x reference)
#include <cuda_runtime.h>

// Quanv layer, circuit collapsed to per-qubit Bloch components + Pauli strings:
//   out_q = cos(p_{3+q}) * <Z_q>_w  -  sin(p_{3+q}) * <X_q>_w
// Patch trig done with FMA-pipe polynomials (angles are pi*a, a in [0,1)),
// freeing the MUFU pipe. 8 patches/thread, one wave of 588 CTAs.

// s = sin(pi*a), c = cos(pi*a) for a in [0,1), via u = a - 0.5:
//   sin(pi a) =  cos(pi u)  (even poly in u^2, deg 10, err < 5e-7)
//   cos(pi a) = -sin(pi u)  (odd poly,  deg 11, err < 6e-8)
__device__ __forceinline__ void sincospi01(float a, float& s, float& c)
{
    float u = a - 0.5f;
    float x = u * u;

    float pc = fmaf(x, -0.0258068914f, 0.2353306304f);
    pc = fmaf(pc, x, -1.3352627689f);
    pc = fmaf(pc, x,  4.0587121264f);
    pc = fmaf(pc, x, -4.9348022005f);
    s  = fmaf(pc, x,  1.0f);

    float q = fmaf(x, -0.0023460875f, 0.0261478475f);
    q = fmaf(q, x, -0.1907518241f);
    q = fmaf(q, x,  0.8117424253f);
    q = fmaf(q, x, -1.6449340668f);
    q = fmaf(q, x,  1.0f);
    c = -3.14159265358979f * u * q;
}

__device__ __forceinline__ float4 quanv_one(
    float4 a, float Cp0, float Sp1, float Cp1, float Cp2,
    float4 C, float4 S)
{
    // Per-qubit Bloch (x, z) after encoding RY(pi*a_q) + layer-1 gate.
    float s0, c0; sincospi01(a.x, s0, c0);
    float x0 = s0;                        // RX leaves X
    float z0 = Cp0 * c0;                  // RX: z' = cos(p0)*z (y = 0)

    float s1p, c1p; sincospi01(a.y, s1p, c1p);
    float x1 = fmaf(s1p, Cp1,  c1p * Sp1);   // sin(pi a1 + p1)
    float z1 = fmaf(c1p, Cp1, -s1p * Sp1);   // cos(pi a1 + p1)

    float s2, c2; sincospi01(a.z, s2, c2);
    float x2 = Cp2 * s2;                  // RZ: x' = cos(p2)*x
    float z2 = c2;                        // RZ leaves Z

    float s3, c3; sincospi01(a.w, s3, c3);
    float x3 = c3;                        // H swaps X <-> Z
    float z3 = s3;

    // Pauli strings after conjugating Z_q / X_q through the CNOT ring.
    float z01 = z0 * z1;
    float z23 = z2 * z3;
    float Z0w = z1 * z23;                 // Z1 Z2 Z3
    float Z1w = z01;                      // Z0 Z1
    float Z2w = z01 * z2;                 // Z0 Z1 Z2
    float Z3w = z01 * z23;                // Z0 Z1 Z2 Z3

    float x01 = x0 * x1;
    float X0w = x01;                      // X0 X1
    float X1w = x1 * x2;                  // X1 X2
    float X2w = x2 * x3;                  // X2 X3
    float X3w = x01 * x3;                 // X0 X1 X3

    float4 o;
    o.x = fmaf(C.x, Z0w, -S.x * X0w);
    o.y = fmaf(C.y, Z1w, -S.y * X1w);
    o.z = fmaf(C.z, Z2w, -S.z * X2w);
    o.w = fmaf(C.w, Z3w, -S.w * X3w);
    return o;
}

__global__ __launch_bounds__(256) void quanv_kernel(
    const float* __restrict__ x,      // [n, 4] angles
    const float* __restrict__ params, // [7]
    float* __restrict__ out,          // [n, 4]
    int n)
{
    int eighth = n >> 3;
    int idx = blockIdx.x * blockDim.x + threadIdx.x;

    const float4* xin = (const float4*)x;
    float4* xout = (float4*)out;

    // Front-batch 8 independent LDG.128 (MLP = 8).
    float4 a[8];
    bool main_lane = (idx < eighth);
    if (main_lane) {
        #pragma unroll
        for (int k = 0; k < 8; k++)
            a[k] = xin[idx + k * eighth];
    }

    // Uniform param constants (broadcast loads + 12 MUFU, overlapped with loads).
    float p0 = __ldg(params + 0);
    float p1 = __ldg(params + 1);
    float p2 = __ldg(params + 2);
    float p3 = __ldg(params + 3);
    float p4 = __ldg(params + 4);
    float p5 = __ldg(params + 5);
    float p6 = __ldg(params + 6);

    float Cp0 = __cosf(p0);
    float Sp1 = __sinf(p1);
    float Cp1 = __cosf(p1);
    float Cp2 = __cosf(p2);
    float4 C, S;
    C.x = __cosf(p3); S.x = __sinf(p3);
    C.y = __cosf(p4); S.y = __sinf(p4);
    C.z = __cosf(p5); S.z = __sinf(p5);
    C.w = __cosf(p6); S.w = __sinf(p6);

    if (main_lane) {
        #pragma unroll
        for (int k = 0; k < 8; k++)
            xout[idx + k * eighth] = quanv_one(a[k], Cp0, Sp1, Cp1, Cp2, C, S);
    }

    // Tail for n % 8 != 0 (not hit for this problem's shapes).
    int rem = n - 8 * eighth;
    if (idx < rem) {
        int t = 8 * eighth + idx;
        xout[t] = quanv_one(xin[t], Cp0, Sp1, Cp1, Cp2, C, S);
    }
}

extern "C" void kernel_launch(void* const* d_in, const int* in_sizes, int n_in,
                              void* d_out, int out_size)
{
    const float* x      = (const float*)d_in[0];   // [2048,3,196,4] fp32
    const float* params = (const float*)d_in[1];   // [7] fp32
    float* out = (float*)d_out;                    // flat [n,4] fp32

    int n = in_sizes[0] / 4;       // patches
    int eighth = n >> 3;
    int threads = 256;
    int blocks = (eighth + threads - 1) / threads;
    if (blocks < 1) blocks = 1;
    quanv_kernel<<<blocks, threads>>>(x, params, out, n);
}

// round 7
// speedup vs baseline: 1.1964x; 1.1964x over previous
#include <cuda_runtime.h>

// Quanv layer, circuit collapsed to per-qubit Bloch components + Pauli strings:
//   out_q = cos(p_{3+q}) * <Z_q>_w  -  sin(p_{3+q}) * <X_q>_w
// Single kernel, no barriers. MUFU trig (args in [0, pi+p), abs err ~5e-7,
// tol 1e-3). 2 patches/thread (split-half streams, fully coalesced),
// regs capped at 32 via launch_bounds for max occupancy.

__device__ __forceinline__ float4 quanv_one(
    float4 a, float Cp0, float p1, float Cp2,
    float4 C, float4 S)
{
    const float PI = 3.14159265358979323846f;

    // Per-qubit Bloch (x, z) after encoding RY(pi*a_q) + layer-1 gate.
    float t0 = a.x * PI;
    float x0 = __sinf(t0);              // RX leaves X
    float z0 = Cp0 * __cosf(t0);        // RX: z' = cos(p0) * z   (y = 0)

    float t1 = fmaf(a.y, PI, p1);       // RY(p1) adds angles
    float x1 = __sinf(t1);
    float z1 = __cosf(t1);

    float t2 = a.z * PI;
    float x2 = Cp2 * __sinf(t2);        // RZ: x' = cos(p2) * x
    float z2 = __cosf(t2);              // RZ leaves Z

    float t3 = a.w * PI;
    float x3 = __cosf(t3);              // H swaps X <-> Z
    float z3 = __sinf(t3);

    // Pauli strings after conjugating Z_q / X_q through the CNOT ring.
    float z01 = z0 * z1;
    float z23 = z2 * z3;
    float Z0w = z1 * z23;               // Z1 Z2 Z3
    float Z1w = z01;                    // Z0 Z1
    float Z2w = z01 * z2;               // Z0 Z1 Z2
    float Z3w = z01 * z23;              // Z0 Z1 Z2 Z3

    float x01 = x0 * x1;
    float X0w = x01;                    // X0 X1
    float X1w = x1 * x2;                // X1 X2
    float X2w = x2 * x3;                // X2 X3
    float X3w = x01 * x3;               // X0 X1 X3

    float4 o;
    o.x = fmaf(C.x, Z0w, -S.x * X0w);
    o.y = fmaf(C.y, Z1w, -S.y * X1w);
    o.z = fmaf(C.z, Z2w, -S.z * X2w);
    o.w = fmaf(C.w, Z3w, -S.w * X3w);
    return o;
}

__global__ __launch_bounds__(256, 8) void quanv_kernel(
    const float* __restrict__ x,      // [n, 4] angles
    const float* __restrict__ params, // [7]
    float* __restrict__ out,          // [n, 4]
    int n)
{
    int half = n >> 1;
    int idx = blockIdx.x * blockDim.x + threadIdx.x;

    const float4* xin = (const float4*)x;
    float4* xout = (float4*)out;

    // Front-batch the two patch loads (independent -> MLP=2, in flight
    // while the param prologue computes).
    float4 a0, a1;
    bool main_lane = (idx < half);
    if (main_lane) {
        a0 = xin[idx];
        a1 = xin[idx + half];
    }

    // Uniform param constants (broadcast loads + MUFU).
    float p0 = __ldg(params + 0);
    float p1 = __ldg(params + 1);
    float p2 = __ldg(params + 2);
    float p3 = __ldg(params + 3);
    float p4 = __ldg(params + 4);
    float p5 = __ldg(params + 5);
    float p6 = __ldg(params + 6);

    float Cp0 = __cosf(p0);
    float Cp2 = __cosf(p2);
    float4 C, S;
    C.x = __cosf(p3); S.x = __sinf(p3);
    C.y = __cosf(p4); S.y = __sinf(p4);
    C.z = __cosf(p5); S.z = __sinf(p5);
    C.w = __cosf(p6); S.w = __sinf(p6);

    if (main_lane) {
        xout[idx]        = quanv_one(a0, Cp0, p1, Cp2, C, S);
        xout[idx + half] = quanv_one(a1, Cp0, p1, Cp2, C, S);
    }

    // Tail for odd n (not hit for this problem's shapes).
    if (idx == 0 && (n & 1)) {
        xout[n - 1] = quanv_one(xin[n - 1], Cp0, p1, Cp2, C, S);
    }
}

extern "C" void kernel_launch(void* const* d_in, const int* in_sizes, int n_in,
                              void* d_out, int out_size)
{
    const float* x      = (const float*)d_in[0];   // [2048,3,196,4] fp32
    const float* params = (const float*)d_in[1];   // [7] fp32
    float* out = (float*)d_out;                    // flat [n,4] fp32

    int n = in_sizes[0] / 4;       // patches
    int half = n >> 1;
    int threads = 256;
    int blocks = (half + threads - 1) / threads;
    if (blocks < 1) blocks = 1;
    quanv_kernel<<<blocks, threads>>>(x, params, out, n);
}